// round 17
// baseline (speedup 1.0000x reference)
#include <cuda_runtime.h>
#include <cuda_bf16.h>
#include <cstdint>

#define T_TOKENS 16384
#define NEXP     64
#define KDIM     4096
#define BM       128        // tokens per CTA (M=128 MMA, proven layout)
#define KSPLIT   2
#define KHALF    (KDIM / KSPLIT)      // 2048
#define KC       64                    // K elems per chunk
#define NC_CTA   (KHALF / KC)          // 32 chunks per CTA
#define NCHUNK   (KDIM / KC)           // 64 total
#define THREADS  256

typedef unsigned long long u64;

#if defined(__CUDA_ARCH_FEAT_SM103_ALL) || defined(__CUDA_ARCH_FEAT_SM100_ALL) || defined(__CUDA_ARCH_FEAT_SM101_ALL)
#define HAS_TCGEN05 1
#else
#define HAS_TCGEN05 0
#endif

// Precomputed W-split B-tile image per chunk: 3 splits x 64 rows x 128B = 24KB
#define B_TILE   (NEXP * 128)           // 8192
#define B_CHUNK  (3 * B_TILE)           // 24576
__device__ u64 Bimg[NCHUNK * B_CHUNK / 8];

// Partial logits scratch: [ksplit][token][expert] fp32 = 8MB
__device__ float Pscr[KSPLIT][T_TOKENS][NEXP];

// smem: B double buffer only (A lives in TMEM now)
#define SMEM_DYN (1024 + 2 * B_CHUNK)   // 50176 -> 2 CTAs/SM easily

#define SW128(o) ((o) ^ (((o) >> 3) & 0x70))

// TMEM layout: D at cols [0,64), A at cols [64,160) (3 splits x 32 cols)
#define TMEM_D_OFF 0
#define TMEM_A_OFF 64
#define TMEM_COLS  256

// ---------------- portable helpers ----------------
__device__ __forceinline__ u64 ffma2(u64 a, u64 b, u64 c) {
    u64 d; asm("fma.rn.f32x2 %0, %1, %2, %3;" : "=l"(d) : "l"(a), "l"(b), "l"(c)); return d;
}
__device__ __forceinline__ u64 pack2f(float lo, float hi) {
    u64 d; asm("mov.b64 %0, {%1, %2};" : "=l"(d) : "f"(lo), "f"(hi)); return d;
}
__device__ __forceinline__ void unpack2f(u64 v, float& lo, float& hi) {
    asm("mov.b64 {%0, %1}, %2;" : "=f"(lo), "=f"(hi) : "l"(v));
}
__device__ __forceinline__ uint32_t cvt_bf2(float lo, float hi) {
    uint32_t r; asm("cvt.rn.bf16x2.f32 %0, %1, %2;" : "=r"(r) : "f"(hi), "f"(lo)); return r;
}
__device__ __forceinline__ u64 bf2_to_f2(uint32_t p) {
    uint32_t lo = p << 16, hi = p & 0xFFFF0000u;
    u64 d; asm("mov.b64 %0, {%1, %2};" : "=l"(d) : "r"(lo), "r"(hi)); return d;
}
__device__ __forceinline__ u64 pk32(uint32_t lo, uint32_t hi) {
    u64 d; asm("mov.b64 %0, {%1, %2};" : "=l"(d) : "r"(lo), "r"(hi)); return d;
}
__device__ __forceinline__ uint32_t smem_u32(const void* p) {
    uint32_t a;
    asm("{ .reg .u64 t; cvta.to.shared.u64 t, %1; cvt.u32.u64 %0, t; }" : "=r"(a) : "l"(p));
    return a;
}
__device__ __forceinline__ void cpasync16(uint32_t dst, const void* src) {
    asm volatile("cp.async.cg.shared.global [%0], [%1], 16;" :: "r"(dst), "l"(src) : "memory");
}
#define CP_COMMIT() asm volatile("cp.async.commit_group;" ::: "memory")
#define CP_WAIT0()  asm volatile("cp.async.wait_group 0;" ::: "memory")

// 3-way bf16 split of two adjacent floats -> three packed bf16x2 words
__device__ __forceinline__ void split3_2(float a, float b,
                                         uint32_t& q0, uint32_t& q1, uint32_t& q2) {
    const u64 M1 = 0xBF800000BF800000ULL;  // {-1.0f, -1.0f}
    u64 xp = pack2f(a, b);
    q0 = cvt_bf2(a, b);
    u64 r1 = ffma2(bf2_to_f2(q0), M1, xp);
    float r1l, r1h; unpack2f(r1, r1l, r1h);
    q1 = cvt_bf2(r1l, r1h);
    u64 r2 = ffma2(bf2_to_f2(q1), M1, r1);
    float r2l, r2h; unpack2f(r2, r2l, r2h);
    q2 = cvt_bf2(r2l, r2h);
}

#if HAS_TCGEN05
// idesc kind::f16: dtype=F32, atype=BF16, btype=BF16, N=64, M=128  (proven)
static constexpr uint32_t IDESC =
    (1u << 4) | (1u << 7) | (1u << 10) | ((NEXP / 8) << 17) | ((BM / 16) << 24); // 0x8100490

__device__ __forceinline__ uint32_t elect1() {
    uint32_t p;
    asm volatile("{ .reg .pred p; elect.sync _|p, 0xFFFFFFFF; selp.b32 %0,1,0,p; }" : "=r"(p));
    return p;
}
__device__ __forceinline__ u64 mkdesc(uint32_t addr) {  // SW128, LBO=1, SBO=64, version=1
    const u64 base = (2ULL << 61) | (1ULL << 46) | (64ULL << 32) | (1ULL << 16);
    return base | ((addr >> 4) & 0x3FFF);
}
// TS form: A in TMEM, B in SMEM (pattern from test_mma.cu / test_mma_iter.cu)
__device__ __forceinline__ void mma_f16_ts(uint32_t d, uint32_t a_tmem, u64 bd, uint32_t en) {
    asm volatile(
        "{\n\t.reg .pred p;\n\tsetp.ne.u32 p, %5, 0;\n\t"
        "tcgen05.mma.cta_group::1.kind::f16 [%0], [%1], %2, %3, {%4,%4,%4,%4}, p;\n\t}"
        :: "r"(d), "r"(a_tmem), "l"(bd), "r"(IDESC), "r"(0u), "r"(en) : "memory");
}
#define MBAR_INIT(a, n) asm volatile("mbarrier.init.shared.b64 [%0], %1;" :: "r"(a), "r"(n) : "memory")
#define TCG_COMMIT(a) \
    asm volatile("tcgen05.commit.cta_group::1.mbarrier::arrive::one.shared::cluster.b64 [%0];" \
                 :: "r"(a) : "memory")
#define MBAR_WAIT(mbar, par) do {                                                   \
    uint32_t _m = (mbar), _p = (uint32_t)(par), _d;                                 \
    asm volatile("{\n\t.reg .pred p;\n\t"                                           \
        "mbarrier.try_wait.parity.acquire.cta.shared::cta.b64 p, [%1], %2;\n\t"     \
        "selp.b32 %0, 1, 0, p;\n\t}" : "=r"(_d) : "r"(_m), "r"(_p) : "memory");     \
    if (!_d) {                                                                      \
        asm volatile("{\n\t.reg .pred P1;\n\t"                                      \
            "W_%=:\n\t"                                                             \
            "mbarrier.try_wait.parity.acquire.cta.shared::cta.b64 P1, [%0], %1, 0x989680;\n\t" \
            "@P1 bra.uni D_%=;\n\t"                                                 \
            "bra.uni W_%=;\n\t"                                                     \
            "D_%=:\n\t}" :: "r"(_m), "r"(_p) : "memory");                           \
    } } while (0)
#define TCG_ALLOC(sm, n)  asm volatile("tcgen05.alloc.cta_group::1.sync.aligned.shared::cta.b32 [%0], %1;" :: "r"(sm), "r"(n) : "memory")
#define TCG_RELINQ()      asm volatile("tcgen05.relinquish_alloc_permit.cta_group::1.sync.aligned;")
#define TCG_DEALLOC(t, n) asm volatile("tcgen05.dealloc.cta_group::1.sync.aligned.b32 %0, %1;" :: "r"(t), "r"(n))
#define TCG_FENCE_AFTER() asm volatile("tcgen05.fence::after_thread_sync;" ::: "memory")
#define TCG_WAIT_LD()     asm volatile("tcgen05.wait::ld.sync.aligned;" ::: "memory")
#define TCG_WAIT_ST()     asm volatile("tcgen05.wait::st.sync.aligned;" ::: "memory")

#define STTM16(addr, r) \
    asm volatile("tcgen05.st.sync.aligned.32x32b.x16.b32 [%0], " \
        "{%1,%2,%3,%4,%5,%6,%7,%8,%9,%10,%11,%12,%13,%14,%15,%16};" \
        :: "r"(addr), \
           "r"((r)[0]),"r"((r)[1]),"r"((r)[2]),"r"((r)[3]), \
           "r"((r)[4]),"r"((r)[5]),"r"((r)[6]),"r"((r)[7]), \
           "r"((r)[8]),"r"((r)[9]),"r"((r)[10]),"r"((r)[11]), \
           "r"((r)[12]),"r"((r)[13]),"r"((r)[14]),"r"((r)[15]) : "memory")

#define LDTM32(r, addr) \
    asm volatile("tcgen05.ld.sync.aligned.32x32b.x32.b32 " \
        "{%0,%1,%2,%3,%4,%5,%6,%7,%8,%9,%10,%11,%12,%13,%14,%15," \
        "%16,%17,%18,%19,%20,%21,%22,%23,%24,%25,%26,%27,%28,%29,%30,%31}, [%32];" \
        : "=r"((r)[0]),"=r"((r)[1]),"=r"((r)[2]),"=r"((r)[3]),"=r"((r)[4]),"=r"((r)[5]), \
          "=r"((r)[6]),"=r"((r)[7]),"=r"((r)[8]),"=r"((r)[9]),"=r"((r)[10]),"=r"((r)[11]), \
          "=r"((r)[12]),"=r"((r)[13]),"=r"((r)[14]),"=r"((r)[15]),"=r"((r)[16]),"=r"((r)[17]), \
          "=r"((r)[18]),"=r"((r)[19]),"=r"((r)[20]),"=r"((r)[21]),"=r"((r)[22]),"=r"((r)[23]), \
          "=r"((r)[24]),"=r"((r)[25]),"=r"((r)[26]),"=r"((r)[27]),"=r"((r)[28]),"=r"((r)[29]), \
          "=r"((r)[30]),"=r"((r)[31]) : "r"(addr))
#endif  // HAS_TCGEN05

// ---------------- W split B-tile image precompute ----------------
__global__ void wimg_kernel(const float* __restrict__ W) {
#if HAS_TCGEN05
    int idx = blockIdx.x * blockDim.x + threadIdx.x;   // (chunk, expert, u64 group)
    if (idx >= NCHUNK * NEXP * 16) return;
    int c = idx >> 10;
    int r = (idx >> 4) & 63;
    int j = idx & 15;
    const float* p = W + (size_t)r * KDIM + c * KC + j * 4;
    uint32_t a0, a1, a2, b0, b1, b2;
    split3_2(p[0], p[1], a0, a1, a2);
    split3_2(p[2], p[3], b0, b1, b2);
    uint32_t off = SW128((uint32_t)(r * 128 + j * 8));
    u64* base = &Bimg[((size_t)c * B_CHUNK) >> 3];
    base[(0 * B_TILE + off) >> 3] = pk32(a0, b0);
    base[(1 * B_TILE + off) >> 3] = pk32(a1, b1);
    base[(2 * B_TILE + off) >> 3] = pk32(a2, b2);
#endif
}

// ---------------- main GEMM kernel (K-split partials, TS-mode A in TMEM) ----------------
__global__ __launch_bounds__(THREADS, 2)
void router_mma(const float* __restrict__ x,
                const float* __restrict__ W)
{
    const int bx = blockIdx.x;
    const int tb = bx >> 1;           // token tile 0..127
    const int ks = bx & 1;            // K-split half
    const int t0 = tb * BM;
    const int c0 = ks * NC_CTA;       // absolute chunk base

#if HAS_TCGEN05
    extern __shared__ char dsm[];
    __shared__ uint32_t s_tmem;
    __shared__ __align__(8) u64 s_mbar;

    const int tid  = threadIdx.x;
    const int wid  = tid >> 5;
    const int lane = tid & 31;
    const int sub  = wid & 3;         // TMEM subpartition (lane block)
    const int kh   = wid >> 2;        // K-half within chunk: 0 -> K[0,32), 1 -> K[32,64)
    const int row  = sub * 32 + lane; // token row (lane = row within subpartition)

    const uint32_t dbase = (smem_u32(dsm) + 1023u) & ~1023u;

    if (wid == 0) TCG_ALLOC(smem_u32(&s_tmem), TMEM_COLS);
    if (tid == 0) MBAR_INIT(smem_u32(&s_mbar), 1);
    __syncthreads();
    const uint32_t tmem = s_tmem;
    if (wid == 0) TCG_RELINQ();
    const uint32_t mb = smem_u32(&s_mbar);
    int ph = 0;

    const uint32_t warp_off = (uint32_t)sub << 21;
    const uint32_t aT = tmem + TMEM_A_OFF + (uint32_t)kh * 16;   // + split*32 later

    const float* xrow = x + (size_t)(t0 + row) * KDIM + (size_t)ks * KHALF + kh * 32;

    // prefetch B(0)
    {
        const char* src = (const char*)Bimg + (size_t)c0 * B_CHUNK;
        const uint32_t bB = dbase;
#pragma unroll
        for (int i = 0; i < 6; i++) {
            int idx = tid + i * THREADS;
            cpasync16(bB + idx * 16, src + idx * 16);
        }
        CP_COMMIT();
    }

#pragma unroll 1
    for (int c = 0; c < NC_CTA; ++c) {
        // LDG this thread's 32 contiguous floats (one row segment) — overlaps wait
        float f[32];
        {
            const float4* xp = (const float4*)(xrow + c * KC);
#pragma unroll
            for (int i = 0; i < 8; i++) {
                float4 v = xp[i];
                f[4 * i + 0] = v.x; f[4 * i + 1] = v.y;
                f[4 * i + 2] = v.z; f[4 * i + 3] = v.w;
            }
        }
        // convert to 3 bf16 splits in registers
        uint32_t q0[16], q1[16], q2[16];
#pragma unroll
        for (int j = 0; j < 16; j++)
            split3_2(f[2 * j], f[2 * j + 1], q0[j], q1[j], q2[j]);

        // single-buffered A in TMEM: previous chunk's MMA must be done
        if (c >= 1) { MBAR_WAIT(mb, ph); ph ^= 1; }

        // store A splits to TMEM (separate port, 256B/cyc)
        STTM16(aT + 0 * 32 + warp_off, q0);
        STTM16(aT + 1 * 32 + warp_off, q1);
        STTM16(aT + 2 * 32 + warp_off, q2);
        TCG_WAIT_ST();

        CP_WAIT0();   // B(c) resident
        asm volatile("fence.proxy.async.shared::cta;" ::: "memory");
        __syncthreads();

        if (wid == 0 && elect1()) {
            const uint32_t bB = dbase + (uint32_t)(c & 1) * B_CHUNK;
            u64 bd0 = mkdesc(bB), bd1 = mkdesc(bB + B_TILE), bd2 = mkdesc(bB + 2 * B_TILE);
            const uint32_t a0 = tmem + TMEM_A_OFF + 0 * 32;
            const uint32_t a1 = tmem + TMEM_A_OFF + 1 * 32;
            const uint32_t a2 = tmem + TMEM_A_OFF + 2 * 32;
            const uint32_t dT = tmem + TMEM_D_OFF;
#pragma unroll
            for (int kstep = 0; kstep < 4; kstep++) {   // K=16 per dispatch: 8 TMEM cols, 2 desc units
                uint32_t ao = kstep * 8;
                u64 o = 2 * kstep;
                mma_f16_ts(dT, a0 + ao, bd0 + o, (c == 0 && kstep == 0) ? 0u : 1u);
                mma_f16_ts(dT, a0 + ao, bd1 + o, 1u);
                mma_f16_ts(dT, a1 + ao, bd0 + o, 1u);
                mma_f16_ts(dT, a0 + ao, bd2 + o, 1u);
                mma_f16_ts(dT, a1 + ao, bd1 + o, 1u);
                mma_f16_ts(dT, a2 + ao, bd0 + o, 1u);
            }
            TCG_COMMIT(mb);
        }

        // prefetch B(c+1) into the other buffer (overlaps MMA + next LDG/convert)
        if (c + 1 < NC_CTA) {
            const char* src = (const char*)Bimg + (size_t)(c0 + c + 1) * B_CHUNK;
            const uint32_t bB = dbase + (uint32_t)((c + 1) & 1) * B_CHUNK;
#pragma unroll
            for (int i = 0; i < 6; i++) {
                int idx = tid + i * THREADS;
                cpasync16(bB + idx * 16, src + idx * 16);
            }
            CP_COMMIT();
        }
    }

    MBAR_WAIT(mb, ph);
    TCG_FENCE_AFTER();

    if (wid < 4) {   // M=128: lane = token row (proven layout)
        uint32_t dr[64];
        LDTM32(dr, tmem + TMEM_D_OFF);
        LDTM32(dr + 32, tmem + TMEM_D_OFF + 32);
        TCG_WAIT_LD();

        int t = t0 + wid * 32 + lane;
        float4* dst = (float4*)&Pscr[ks][t][0];
#pragma unroll
        for (int j = 0; j < 16; j++) {
            float4 v;
            v.x = __uint_as_float(dr[4 * j + 0]);
            v.y = __uint_as_float(dr[4 * j + 1]);
            v.z = __uint_as_float(dr[4 * j + 2]);
            v.w = __uint_as_float(dr[4 * j + 3]);
            dst[j] = v;
        }
    }

    __syncthreads();
    if (wid == 0) TCG_DEALLOC(tmem, TMEM_COLS);

#else
    // ============== fallback: FFMA f32x2 partials over this CTA's K-half ==============
    extern __shared__ char dsm[];
    struct SmG { float xs[32][64 + 2]; float ws[32][64 + 4]; };
    SmG* g = (SmG*)dsm;

    const int tid = threadIdx.x;
    const int tm = (tid >> 4) << 2;
    const int tn = (tid & 15) << 2;

#pragma unroll 1
    for (int h = 0; h < 2; h++) {
        const int tt0 = t0 + h * 64;

        u64 acc[2][4];
#pragma unroll
        for (int p = 0; p < 2; p++)
#pragma unroll
            for (int j = 0; j < 4; j++) acc[p][j] = 0ULL;

        __syncthreads();

#pragma unroll 1
        for (int kb = ks * KHALF; kb < (ks + 1) * KHALF; kb += 32) {
#pragma unroll
            for (int i = 0; i < 2; i++) {
                int idx = tid + i * 256;
                int rrow = idx >> 3;
                int c4  = (idx & 7) << 2;
                float4 v = *(const float4*)&x[(size_t)(tt0 + rrow) * KDIM + kb + c4];
                g->xs[c4 + 0][rrow] = v.x;
                g->xs[c4 + 1][rrow] = v.y;
                g->xs[c4 + 2][rrow] = v.z;
                g->xs[c4 + 3][rrow] = v.w;
                float4 wv = *(const float4*)&W[(size_t)rrow * KDIM + kb + c4];
                g->ws[c4 + 0][rrow] = wv.x;
                g->ws[c4 + 1][rrow] = wv.y;
                g->ws[c4 + 2][rrow] = wv.z;
                g->ws[c4 + 3][rrow] = wv.w;
            }
            __syncthreads();

#pragma unroll
            for (int k = 0; k < 32; k++) {
                u64 x01 = *(const u64*)&g->xs[k][tm];
                u64 x23 = *(const u64*)&g->xs[k][tm + 2];
                float4 wv = *(const float4*)&g->ws[k][tn];
                u64 w0 = pack2f(wv.x, wv.x);
                u64 w1 = pack2f(wv.y, wv.y);
                u64 w2 = pack2f(wv.z, wv.z);
                u64 w3 = pack2f(wv.w, wv.w);
                acc[0][0] = ffma2(x01, w0, acc[0][0]);
                acc[1][0] = ffma2(x23, w0, acc[1][0]);
                acc[0][1] = ffma2(x01, w1, acc[0][1]);
                acc[1][1] = ffma2(x23, w1, acc[1][1]);
                acc[0][2] = ffma2(x01, w2, acc[0][2]);
                acc[1][2] = ffma2(x23, w2, acc[1][2]);
                acc[0][3] = ffma2(x01, w3, acc[0][3]);
                acc[1][3] = ffma2(x23, w3, acc[1][3]);
            }
            __syncthreads();
        }

#pragma unroll
        for (int p = 0; p < 2; p++)
#pragma unroll
            for (int j = 0; j < 4; j++) {
                float lo, hi;
                unpack2f(acc[p][j], lo, hi);
                Pscr[ks][tt0 + tm + 2 * p + 0][tn + j] = lo;
                Pscr[ks][tt0 + tm + 2 * p + 1][tn + j] = hi;
            }
    }
#endif
}

// ---------------- combine + top2 + softmax (portable, deterministic) ----------------
__global__ void combine_kernel(float* __restrict__ out) {
    int t = blockIdx.x * blockDim.x + threadIdx.x;
    if (t >= T_TOKENS) return;

    const float4* p0 = (const float4*)&Pscr[0][t][0];
    const float4* p1 = (const float4*)&Pscr[1][t][0];
    float fv[NEXP];
#pragma unroll
    for (int j = 0; j < 16; j++) {
        float4 a = p0[j], b = p1[j];
        fv[4 * j + 0] = a.x + b.x;
        fv[4 * j + 1] = a.y + b.y;
        fv[4 * j + 2] = a.z + b.z;
        fv[4 * j + 3] = a.w + b.w;
    }

    float b1 = -3.4e38f; int i1 = 0;
#pragma unroll
    for (int e = 0; e < NEXP; e++) if (fv[e] > b1) { b1 = fv[e]; i1 = e; }
    float b2 = -3.4e38f; int i2 = 0;
#pragma unroll
    for (int e = 0; e < NEXP; e++) if (e != i1 && fv[e] > b2) { b2 = fv[e]; i2 = e; }

    float s1 = 1.0f / (1.0f + expf(b2 - b1));
    float s2 = 1.0f - s1;

    out[2 * t + 0] = s1;
    out[2 * t + 1] = s2;
    out[2 * T_TOKENS + 2 * t + 0] = (float)i1;
    out[2 * T_TOKENS + 2 * t + 1] = (float)i2;
}

extern "C" void kernel_launch(void* const* d_in, const int* in_sizes, int n_in,
                              void* d_out, int out_size) {
    const float* x = (const float*)d_in[0];
    const float* W = (const float*)d_in[1];
    float* out = (float*)d_out;

    cudaFuncSetAttribute(router_mma, cudaFuncAttributeMaxDynamicSharedMemorySize, SMEM_DYN);

    wimg_kernel<<<(NCHUNK * NEXP * 16 + 255) / 256, 256>>>(W);
    router_mma<<<(T_TOKENS / BM) * KSPLIT, THREADS, SMEM_DYN>>>(x, W);
    combine_kernel<<<T_TOKENS / 256, 256>>>(out);
}